// round 12
// baseline (speedup 1.0000x reference)
#include <cuda_runtime.h>
#include <math.h>

// ---------------- static configuration ----------------
#define BATCH   4
#define A_TOTAL 159882
#define NLEV    5
#define K_ALL   4507
#define POST_N  1000
#define IMG_WF  800.0f
#define IMG_HF  800.0f
#define MIN_SZ  0.001f
#define NMS_T   0.7f
#define BBOX_CLIP 4.135166556742356f
#define FILL_RB 16           // row-blocks of 64 rows (2 per warp) per (img,lev)
#define NW      16           // 64-bit words per suppression row (ceil(1000/64))
#define NINST   (BATCH * NLEV)

__constant__ int c_n[NLEV]    = {120000, 30000, 7500, 1875, 507};
__constant__ int c_off[NLEV]  = {0, 120000, 150000, 157500, 159375};
__constant__ int c_k[NLEV]    = {1000, 1000, 1000, 1000, 507};
__constant__ int c_soff[NLEV] = {0, 1000, 2000, 3000, 4000};

// ---------------- scratch (device globals; zero-init at load) --------------
__device__ unsigned           g_hist  [NINST * 4096];
__device__ float4             g_boxv  [BATCH * K_ALL];   // clipped boxes
__device__ float              g_scorev[BATCH * K_ALL];   // sigmoid scores
__device__ unsigned           g_keyv  [BATCH * K_ALL];   // mono(obj) if valid else 0
__device__ int                g_maxc  [BATCH];           // float bits (coords >= 0)
__device__ unsigned long long g_sup   [NINST * 1000 * NW];
__device__ unsigned           g_rowmask[NINST * 1000];   // nonzero-word mask per row
__device__ unsigned long long g_keepbits[NINST * NW];

__device__ __forceinline__ unsigned mono_bits(float f) {
    unsigned u = __float_as_uint(f);
    return (u & 0x80000000u) ? ~u : (u | 0x80000000u);
}

// in-shared-memory bitonic sort, descending, m = power of 2
__device__ __forceinline__ void bitonic_desc(unsigned long long* keys, int m, int t, int NT) {
    for (int k = 2; k <= m; k <<= 1) {
        for (int j = k >> 1; j > 0; j >>= 1) {
            for (int i = t; i < m; i += NT) {
                int ix = i ^ j;
                if (ix > i) {
                    unsigned long long a = keys[i], b = keys[ix];
                    bool desc = ((i & k) == 0);
                    if (desc ? (a < b) : (a > b)) { keys[i] = b; keys[ix] = a; }
                }
            }
            __syncthreads();
        }
    }
}

extern __shared__ unsigned char dynsm[];

// ================= Kernel 0: flat histogram (all SMs, global RED) ==========
__global__ void __launch_bounds__(256)
hist_kernel(const float* __restrict__ obj) {
    int base = (blockIdx.x * 256 + threadIdx.x) * 4;
    if (base >= BATCH * A_TOTAL) return;
    #pragma unroll
    for (int e = 0; e < 4; e++) {
        int g = base + e;
        int img = g / A_TOTAL;
        int r = g - img * A_TOTAL;
        int lev = (r < 120000) ? 0 : (r < 150000) ? 1 : (r < 157500) ? 2 :
                  (r < 159375) ? 3 : 4;
        unsigned u = mono_bits(obj[g]);
        atomicAdd(&g_hist[(img * NLEV + lev) * 4096 + (u >> 20)], 1u);
    }
}

// ================= Kernel 1: select + compact + sort + inline decode =======
__global__ void __launch_bounds__(1024, 1)
select_kernel(const float* __restrict__ obj,
              const float4* __restrict__ deltas,
              const float4* __restrict__ anchors) {
    unsigned long long* cand = (unsigned long long*)dynsm;            // 8192 (64KB)
    unsigned*           hist = (unsigned*)(dynsm + 65536);            // 4096 (16KB)
    int*                sA   = (int*)(dynsm + 65536 + 16384);         // 1024
    int*                sB   = sA + 1024;                             // 1024
    __shared__ int sh_B, sh_cnt;

    const int inst = blockIdx.x;           // 0..19
    const int img = inst / NLEV;
    const int lev = inst % NLEV;
    const int n = c_n[lev], lvoff = c_off[lev], k = c_k[lev], soff = c_soff[lev];
    const float* __restrict__ src = obj + img * A_TOTAL + lvoff;
    const int t = threadIdx.x, NT = blockDim.x;

    for (int b = t; b < 4096; b += NT) {
        hist[b] = g_hist[inst * 4096 + b];
        g_hist[inst * 4096 + b] = 0u;       // re-zero for next replay
    }
    __syncthreads();

    // segment sums (4 buckets each) + parallel suffix-inclusive scan
    {
        int base = t * 4;
        sA[t] = (int)(hist[base] + hist[base + 1] + hist[base + 2] + hist[base + 3]);
    }
    __syncthreads();
    {
        int* pin = sA; int* pout = sB;
        for (int d = 1; d < 1024; d <<= 1) {
            int v = pin[t];
            if (t + d < 1024) v += pin[t + d];
            pout[t] = v;
            __syncthreads();
            int* tmp = pin; pin = pout; pout = tmp;
        }
        int suffIncl  = pin[t];
        int suffAfter = (t < 1023) ? pin[t + 1] : 0;
        if (suffIncl >= k && suffAfter < k) {
            int cum = suffAfter, B = 4 * t;
            for (int bb = 4 * t + 3; bb >= 4 * t; bb--) {
                if (cum + (int)hist[bb] >= k) { B = bb; break; }
                cum += (int)hist[bb];
            }
            sh_B = B;
            sh_cnt = 0;
        }
    }
    __syncthreads();

    const int B = sh_B;
    for (int j = t; j < n; j += NT) {
        unsigned u = mono_bits(src[j]);
        if ((int)(u >> 20) >= B) {
            int p = atomicAdd(&sh_cnt, 1);
            if (p < 8192)
                cand[p] = ((unsigned long long)u << 32) | (unsigned)(~(unsigned)j);
        }
    }
    __syncthreads();

    int cnt = sh_cnt;
    if (cnt > 8192) cnt = 8192;
    int m = 1;
    while (m < cnt || m < k) m <<= 1;
    if (m > 8192) m = 8192;
    for (int i = cnt + t; i < m; i += NT) cand[i] = 0ULL;
    __syncthreads();

    bitonic_desc(cand, m, t, NT);

    // inline decode of the k selected candidates
    for (int s = t; s < k; s += NT) {
        int j = (int)(~(unsigned)cand[s]);     // local index (ties asc = lax.top_k)
        int idx = lvoff + j;
        int g = img * K_ALL + soff + s;

        float  o = obj[img * A_TOTAL + idx];
        float4 d = deltas[img * A_TOTAL + idx];
        float4 a = anchors[idx];

        float wa  = __fsub_rn(a.z, a.x);
        float ha  = __fsub_rn(a.w, a.y);
        float cxa = __fadd_rn(a.x, __fmul_rn(0.5f, wa));
        float cya = __fadd_rn(a.y, __fmul_rn(0.5f, ha));
        float dw  = fminf(d.z, BBOX_CLIP);
        float dh  = fminf(d.w, BBOX_CLIP);
        float cx  = __fadd_rn(__fmul_rn(d.x, wa), cxa);
        float cy  = __fadd_rn(__fmul_rn(d.y, ha), cya);
        float w   = __fmul_rn(expf(dw), wa);
        float h   = __fmul_rn(expf(dh), ha);
        float x1  = __fsub_rn(cx, __fmul_rn(0.5f, w));
        float y1  = __fsub_rn(cy, __fmul_rn(0.5f, h));
        float x2  = __fadd_rn(cx, __fmul_rn(0.5f, w));
        float y2  = __fadd_rn(cy, __fmul_rn(0.5f, h));

        float x1c = fminf(fmaxf(x1, 0.0f), IMG_WF);
        float y1c = fminf(fmaxf(y1, 0.0f), IMG_HF);
        float x2c = fminf(fmaxf(x2, 0.0f), IMG_WF);
        float y2c = fminf(fmaxf(y2, 0.0f), IMG_HF);

        float score = 1.0f / (1.0f + expf(-o));
        bool valid = (__fsub_rn(x2c, x1c) >= MIN_SZ) &&
                     (__fsub_rn(y2c, y1c) >= MIN_SZ) &&
                     (score >= 0.0f);

        g_boxv[g]   = make_float4(x1c, y1c, x2c, y2c);
        g_scorev[g] = score;
        g_keyv[g]   = valid ? mono_bits(o) : 0u;

        float mx = fmaxf(fmaxf(x1c, y1c), fmaxf(x2c, y2c));
        atomicMax(&g_maxc[img], __float_as_int(mx));
    }
}

// ================= Kernel 2: suppression matrix fill (all SMs) =============
__device__ __forceinline__ bool pair_sup(float4 bi, float ai,
                                         const float4* sbox, const float* sar,
                                         int j, int i, int k) {
    if (j <= i || j >= k) return false;
    float4 bj = sbox[j];
    float lx = fmaxf(bi.x, bj.x), ly = fmaxf(bi.y, bj.y);
    float rx = fminf(bi.z, bj.z), ry = fminf(bi.w, bj.w);
    float ww = fmaxf(__fsub_rn(rx, lx), 0.0f);
    float hh = fmaxf(__fsub_rn(ry, ly), 0.0f);
    float inter = __fmul_rn(ww, hh);
    if (!(inter > 0.0f)) return false;                 // ref: 0/denom=0 or 0/0=NaN -> false
    float denom = __fsub_rn(__fadd_rn(ai, sar[j]), inter);
    float hib = __fmul_rn(denom, 0.7000070f);
    float lob = __fmul_rn(denom, 0.6999930f);
    if (inter > hib && denom >= 0.0f) return true;     // certified > 0.7
    if (inter < lob) return false;                     // certified <= 0.7
    return __fdiv_rn(inter, denom) > NMS_T;            // exact boundary path
}

__device__ __forceinline__ void fill_row(int i, int k, int inst,
                                         const float4* sbox, const float* sar,
                                         int lane) {
    if (i >= k) return;
    float4 bi = sbox[i];
    float  ai = sar[i];
    unsigned long long* dst = &g_sup[(size_t)(inst * 1000 + i) * NW];
    unsigned mask = 0u;

    for (int w = i >> 6; w < NW; w++) {
        int j0 = w * 64 + lane;
        bool bA = pair_sup(bi, ai, sbox, sar, j0,      i, k);
        bool bB = pair_sup(bi, ai, sbox, sar, j0 + 32, i, k);
        unsigned m0 = __ballot_sync(0xffffffffu, bA);
        unsigned m1 = __ballot_sync(0xffffffffu, bB);
        unsigned long long wv = (unsigned long long)m0 | ((unsigned long long)m1 << 32);
        if (wv) {
            mask |= 1u << w;
            if (lane == 0) dst[w] = wv;          // write only nonzero words
        }
    }
    if (lane == 0) g_rowmask[inst * 1000 + i] = mask;
}

__global__ void __launch_bounds__(1024)
nms_fill_kernel() {
    const int bid  = blockIdx.x;
    const int inst = bid / FILL_RB;            // img*NLEV + lev
    const int rb   = bid % FILL_RB;
    const int img  = inst / NLEV, lev = inst % NLEV;
    const int k = c_k[lev], soff = c_soff[lev];
    if (rb * 64 >= k) return;
    const int base = img * K_ALL + soff;

    __shared__ float4 sbox[1000];
    __shared__ float  sar [1000];

    float maxc = __int_as_float(g_maxc[img]);
    float off  = __fmul_rn((float)lev, __fadd_rn(maxc, 1.0f));

    for (int j = threadIdx.x; j < k; j += 1024) {
        float4 b = g_boxv[base + j];
        float x1 = __fadd_rn(b.x, off), y1 = __fadd_rn(b.y, off);
        float x2 = __fadd_rn(b.z, off), y2 = __fadd_rn(b.w, off);
        sbox[j] = make_float4(x1, y1, x2, y2);
        sar[j]  = __fmul_rn(__fsub_rn(x2, x1), __fsub_rn(y2, y1));
    }
    __syncthreads();

    const int warp = threadIdx.x >> 5, lane = threadIdx.x & 31;
    fill_row(rb * 64 + warp,      k, inst, sbox, sar, lane);
    fill_row(rb * 64 + warp + 32, k, inst, sbox, sar, lane);
}

// ================= Kernel 3: chunk-parallel greedy scan =====================
// 16 chunks of 64 candidates. Per chunk: serial 64x64 diagonal resolve in one
// thread (rows prefetched in groups of 8 -> ALU-bound), then a block-parallel
// OR-reduce applies the kept rows' suppression words to later keep-words.
// Boolean-identical to the sequential greedy NMS.
__global__ void __launch_bounds__(1024, 1)
nms_scan_kernel() {
    unsigned long long* ssup = (unsigned long long*)dynsm;          // 1000*NW u64
    unsigned* srm = (unsigned*)(dynsm + 1000 * NW * 8);             // 1000 u32
    __shared__ unsigned long long skeep[NW], sdead[NW], sdiag[NW];
    __shared__ unsigned sv[32], sd[32];
    __shared__ unsigned long long s_alive;

    const int inst = blockIdx.x;
    const int img = inst / NLEV, lev = inst % NLEV;
    const int k = c_k[lev], soff = c_soff[lev];
    const int base = img * K_ALL + soff;
    const int t = threadIdx.x;

    // ---- phase A: sparse load of suppression rows + ballots ----
    bool valid = false, dact = false;
    if (t < k) {
        valid = (g_keyv[base + t] != 0u);
        unsigned m = g_rowmask[inst * 1000 + t];
        srm[t] = m;
        dact = (m >> (t >> 6)) & 1u;       // row suppresses within its own chunk
        const unsigned long long* row = &g_sup[(size_t)(inst * 1000 + t) * NW];
        unsigned mm = m;
        while (mm) {
            int q = __ffs(mm) - 1;
            mm &= mm - 1u;
            ssup[t * NW + q] = row[q];
        }
    }
    unsigned bv = __ballot_sync(0xffffffffu, valid);
    unsigned bd = __ballot_sync(0xffffffffu, dact);
    if ((t & 31) == 0) { sv[t >> 5] = bv; sd[t >> 5] = bd; }
    __syncthreads();
    if (t < NW) {
        skeep[t] = (unsigned long long)sv[2 * t] | ((unsigned long long)sv[2 * t + 1] << 32);
        sdiag[t] = (unsigned long long)sd[2 * t] | ((unsigned long long)sd[2 * t + 1] << 32);
        sdead[t] = 0ULL;
    }
    __syncthreads();

    // ---- phase B: chunk loop ----
    const int NCH = (k + 63) >> 6;
    const int q = t >> 6;          // word this thread applies to (0..15)
    const int i = t & 63;          // row-within-chunk this thread reads

    for (int c = 0; c < NCH; c++) {
        // diagonal resolve (thread 0), groups of 8 with prefetch
        if (t == 0) {
            unsigned long long alive = skeep[c];
            if (alive & sdiag[c]) {
                const int rb = c * 64;
                for (int g = 0; g < 64; g += 8) {
                    unsigned long long rw[8];
                    #pragma unroll
                    for (int e = 0; e < 8; e++) {
                        int r = rb + g + e;
                        rw[e] = (r < k && ((srm[r] >> c) & 1u)) ? ssup[r * NW + c] : 0ULL;
                    }
                    #pragma unroll
                    for (int e = 0; e < 8; e++)
                        if ((alive >> (g + e)) & 1ULL) alive &= ~rw[e];
                }
                skeep[c] = alive;
            }
            s_alive = alive;
        }
        __syncthreads();
        const unsigned long long alive = s_alive;

        // parallel apply: OR of kept rows' word q (q > c) into sdead[q]
        unsigned long long val = 0ULL;
        if (q > c) {
            int r = c * 64 + i;
            if (((alive >> i) & 1ULL) && r < k && ((srm[r] >> q) & 1u))
                val = ssup[r * NW + q];
        }
        #pragma unroll
        for (int d = 16; d > 0; d >>= 1)
            val |= __shfl_xor_sync(0xffffffffu, val, d);
        if ((t & 31) == 0 && val) atomicOr(&sdead[q], val);
        __syncthreads();
        if (t < NW) {
            if (t > c) skeep[t] &= ~sdead[t];
            sdead[t] = 0ULL;
        }
        __syncthreads();
    }

    if (t < NW) g_keepbits[inst * NW + t] = skeep[t];
}

// ================= Kernel 4: rank kept candidates via 5-way merge ===========
__global__ void __launch_bounds__(1024, 1)
final_kernel(float* __restrict__ out) {
    __shared__ unsigned long long klist[K_ALL];
    __shared__ int lvbase[NLEV + 1];
    __shared__ int warpsum[32];

    const int img = blockIdx.x;
    const int t = threadIdx.x;
    const int wid = t >> 5, lane = t & 31;

    for (int x = t; x < POST_N * 4; x += 1024) out[img * POST_N * 4 + x] = 0.0f;
    for (int x = t; x < POST_N; x += 1024) out[BATCH * POST_N * 4 + img * POST_N + x] = 0.0f;
    if (t == 0) { lvbase[0] = 0; g_maxc[img] = 0; }   // re-zero maxc for next replay
    __syncthreads();

    for (int lev = 0; lev < NLEV; lev++) {
        const int k = c_k[lev], soff = c_soff[lev];
        bool kept = false;
        unsigned long long key = 0ULL;
        if (t < k) {
            unsigned long long kb = g_keepbits[(img * NLEV + lev) * NW + (t >> 6)];
            if ((kb >> (t & 63)) & 1ULL) {
                int slot = soff + t;
                kept = true;
                key = ((unsigned long long)g_keyv[img * K_ALL + slot] << 32) |
                      (unsigned)(~(unsigned)slot);
            }
        }
        unsigned bm = __ballot_sync(0xffffffffu, kept);
        if (lane == 0) warpsum[wid] = __popc(bm);
        __syncthreads();
        if (t < 32) {
            int v = warpsum[t];
            for (int d = 1; d < 32; d <<= 1) {
                int o = __shfl_up_sync(0xffffffffu, v, d);
                if (t >= d) v += o;
            }
            warpsum[t] = v;   // inclusive
            if (t == 31) lvbase[lev + 1] = lvbase[lev] + v;
        }
        __syncthreads();
        if (kept) {
            int pos = lvbase[lev] + (wid ? warpsum[wid - 1] : 0) +
                      __popc(bm & ((1u << lane) - 1u));
            klist[pos] = key;
        }
        __syncthreads();
    }

    const int C = lvbase[NLEV];
    for (int c = t; c < C; c += 1024) {
        int lev = 0;
        while (lev < NLEV - 1 && c >= lvbase[lev + 1]) lev++;
        unsigned long long key = klist[c];
        int rank = c - lvbase[lev];
        for (int l2 = 0; l2 < NLEV; l2++) {
            if (l2 == lev) continue;
            int lo = lvbase[l2], hi = lvbase[l2 + 1];
            while (lo < hi) {
                int mid = (lo + hi) >> 1;
                if (klist[mid] > key) lo = mid + 1; else hi = mid;
            }
            rank += lo - lvbase[l2];
        }
        if (rank < POST_N) {
            int slot = (int)(~(unsigned)key);
            float4 b = g_boxv[img * K_ALL + slot];
            float sc = g_scorev[img * K_ALL + slot];
            float* ob = out + (size_t)(img * POST_N + rank) * 4;
            ob[0] = b.x; ob[1] = b.y; ob[2] = b.z; ob[3] = b.w;
            out[BATCH * POST_N * 4 + img * POST_N + rank] = sc;
        }
    }
}

// ================= launch ====================
extern "C" void kernel_launch(void* const* d_in, const int* in_sizes, int n_in,
                              void* d_out, int out_size) {
    const float*  obj     = (const float*) d_in[0];   // [4, 159882]
    const float4* deltas  = (const float4*)d_in[1];   // [4, 159882, 4]
    const float4* anchors = (const float4*)d_in[2];   // [159882, 4]
    float* out = (float*)d_out;                       // boxes[4,1000,4] ++ scores[4,1000]

    cudaFuncSetAttribute(select_kernel,   cudaFuncAttributeMaxDynamicSharedMemorySize, 98304);
    cudaFuncSetAttribute(nms_scan_kernel, cudaFuncAttributeMaxDynamicSharedMemorySize, 135168);

    const int nelem = BATCH * A_TOTAL;                // 639528, divisible by 4
    hist_kernel<<<(nelem / 4 + 255) / 256, 256>>>(obj);
    select_kernel<<<NINST, 1024, 98304>>>(obj, deltas, anchors);
    nms_fill_kernel<<<NINST * FILL_RB, 1024>>>();
    nms_scan_kernel<<<NINST, 1024, 132096>>>();
    final_kernel<<<BATCH, 1024>>>(out);
}

// round 13
// speedup vs baseline: 1.3889x; 1.3889x over previous
#include <cuda_runtime.h>
#include <math.h>

// ---------------- static configuration ----------------
#define BATCH   4
#define A_TOTAL 159882
#define NLEV    5
#define K_ALL   4507
#define POST_N  1000
#define IMG_WF  800.0f
#define IMG_HF  800.0f
#define MIN_SZ  0.001f
#define NMS_T   0.7f
#define BBOX_CLIP 4.135166556742356f
#define FILL_RB 16           // row-blocks of 64 rows (2 per warp) per (img,lev)
#define NW      16           // 64-bit words per suppression row (ceil(1000/64))
#define NINST   (BATCH * NLEV)

__constant__ int c_n[NLEV]    = {120000, 30000, 7500, 1875, 507};
__constant__ int c_off[NLEV]  = {0, 120000, 150000, 157500, 159375};
__constant__ int c_k[NLEV]    = {1000, 1000, 1000, 1000, 507};
__constant__ int c_soff[NLEV] = {0, 1000, 2000, 3000, 4000};

// ---------------- scratch (device globals; zero-init at load) --------------
__device__ unsigned           g_hist  [NINST * 4096];
__device__ float4             g_boxv  [BATCH * K_ALL];   // clipped boxes
__device__ float              g_scorev[BATCH * K_ALL];   // sigmoid scores
__device__ unsigned           g_keyv  [BATCH * K_ALL];   // mono(obj) if valid else 0
__device__ int                g_maxc  [BATCH];           // float bits (coords >= 0)
__device__ unsigned long long g_sup   [NINST * 1000 * NW];
__device__ unsigned           g_rowmask[NINST * 1000];   // nonzero-word mask per row
__device__ unsigned long long g_keepbits[NINST * NW];

__device__ __forceinline__ unsigned mono_bits(float f) {
    unsigned u = __float_as_uint(f);
    return (u & 0x80000000u) ? ~u : (u | 0x80000000u);
}

// in-shared-memory bitonic sort, descending, m = power of 2
__device__ __forceinline__ void bitonic_desc(unsigned long long* keys, int m, int t, int NT) {
    for (int k = 2; k <= m; k <<= 1) {
        for (int j = k >> 1; j > 0; j >>= 1) {
            for (int i = t; i < m; i += NT) {
                int ix = i ^ j;
                if (ix > i) {
                    unsigned long long a = keys[i], b = keys[ix];
                    bool desc = ((i & k) == 0);
                    if (desc ? (a < b) : (a > b)) { keys[i] = b; keys[ix] = a; }
                }
            }
            __syncthreads();
        }
    }
}

extern __shared__ unsigned char dynsm[];

// ================= Kernel 0: flat histogram (all SMs, global RED) ==========
__global__ void __launch_bounds__(256)
hist_kernel(const float* __restrict__ obj) {
    int base = (blockIdx.x * 256 + threadIdx.x) * 4;
    if (base >= BATCH * A_TOTAL) return;
    #pragma unroll
    for (int e = 0; e < 4; e++) {
        int g = base + e;
        int img = g / A_TOTAL;
        int r = g - img * A_TOTAL;
        int lev = (r < 120000) ? 0 : (r < 150000) ? 1 : (r < 157500) ? 2 :
                  (r < 159375) ? 3 : 4;
        unsigned u = mono_bits(obj[g]);
        atomicAdd(&g_hist[(img * NLEV + lev) * 4096 + (u >> 20)], 1u);
    }
}

// ================= Kernel 1: select + compact + sort + inline decode =======
__global__ void __launch_bounds__(1024, 1)
select_kernel(const float* __restrict__ obj,
              const float4* __restrict__ deltas,
              const float4* __restrict__ anchors) {
    unsigned long long* cand = (unsigned long long*)dynsm;            // 8192 (64KB)
    unsigned*           hist = (unsigned*)(dynsm + 65536);            // 4096 (16KB)
    int*                sA   = (int*)(dynsm + 65536 + 16384);         // 1024
    int*                sB   = sA + 1024;                             // 1024
    __shared__ int sh_B, sh_cnt;

    const int inst = blockIdx.x;           // 0..19
    const int img = inst / NLEV;
    const int lev = inst % NLEV;
    const int n = c_n[lev], lvoff = c_off[lev], k = c_k[lev], soff = c_soff[lev];
    const float* __restrict__ src = obj + img * A_TOTAL + lvoff;
    const int t = threadIdx.x, NT = blockDim.x;

    for (int b = t; b < 4096; b += NT) {
        hist[b] = g_hist[inst * 4096 + b];
        g_hist[inst * 4096 + b] = 0u;       // re-zero for next replay
    }
    __syncthreads();

    // segment sums (4 buckets each) + parallel suffix-inclusive scan
    {
        int base = t * 4;
        sA[t] = (int)(hist[base] + hist[base + 1] + hist[base + 2] + hist[base + 3]);
    }
    __syncthreads();
    {
        int* pin = sA; int* pout = sB;
        for (int d = 1; d < 1024; d <<= 1) {
            int v = pin[t];
            if (t + d < 1024) v += pin[t + d];
            pout[t] = v;
            __syncthreads();
            int* tmp = pin; pin = pout; pout = tmp;
        }
        int suffIncl  = pin[t];
        int suffAfter = (t < 1023) ? pin[t + 1] : 0;
        if (suffIncl >= k && suffAfter < k) {
            int cum = suffAfter, B = 4 * t;
            for (int bb = 4 * t + 3; bb >= 4 * t; bb--) {
                if (cum + (int)hist[bb] >= k) { B = bb; break; }
                cum += (int)hist[bb];
            }
            sh_B = B;
            sh_cnt = 0;
        }
    }
    __syncthreads();

    const int B = sh_B;
    for (int j = t; j < n; j += NT) {
        unsigned u = mono_bits(src[j]);
        if ((int)(u >> 20) >= B) {
            int p = atomicAdd(&sh_cnt, 1);
            if (p < 8192)
                cand[p] = ((unsigned long long)u << 32) | (unsigned)(~(unsigned)j);
        }
    }
    __syncthreads();

    int cnt = sh_cnt;
    if (cnt > 8192) cnt = 8192;
    int m = 1;
    while (m < cnt || m < k) m <<= 1;
    if (m > 8192) m = 8192;
    for (int i = cnt + t; i < m; i += NT) cand[i] = 0ULL;
    __syncthreads();

    bitonic_desc(cand, m, t, NT);

    // inline decode of the k selected candidates
    for (int s = t; s < k; s += NT) {
        int j = (int)(~(unsigned)cand[s]);     // local index (ties asc = lax.top_k)
        int idx = lvoff + j;
        int g = img * K_ALL + soff + s;

        float  o = obj[img * A_TOTAL + idx];
        float4 d = deltas[img * A_TOTAL + idx];
        float4 a = anchors[idx];

        float wa  = __fsub_rn(a.z, a.x);
        float ha  = __fsub_rn(a.w, a.y);
        float cxa = __fadd_rn(a.x, __fmul_rn(0.5f, wa));
        float cya = __fadd_rn(a.y, __fmul_rn(0.5f, ha));
        float dw  = fminf(d.z, BBOX_CLIP);
        float dh  = fminf(d.w, BBOX_CLIP);
        float cx  = __fadd_rn(__fmul_rn(d.x, wa), cxa);
        float cy  = __fadd_rn(__fmul_rn(d.y, ha), cya);
        float w   = __fmul_rn(expf(dw), wa);
        float h   = __fmul_rn(expf(dh), ha);
        float x1  = __fsub_rn(cx, __fmul_rn(0.5f, w));
        float y1  = __fsub_rn(cy, __fmul_rn(0.5f, h));
        float x2  = __fadd_rn(cx, __fmul_rn(0.5f, w));
        float y2  = __fadd_rn(cy, __fmul_rn(0.5f, h));

        float x1c = fminf(fmaxf(x1, 0.0f), IMG_WF);
        float y1c = fminf(fmaxf(y1, 0.0f), IMG_HF);
        float x2c = fminf(fmaxf(x2, 0.0f), IMG_WF);
        float y2c = fminf(fmaxf(y2, 0.0f), IMG_HF);

        float score = 1.0f / (1.0f + expf(-o));
        bool valid = (__fsub_rn(x2c, x1c) >= MIN_SZ) &&
                     (__fsub_rn(y2c, y1c) >= MIN_SZ) &&
                     (score >= 0.0f);

        g_boxv[g]   = make_float4(x1c, y1c, x2c, y2c);
        g_scorev[g] = score;
        g_keyv[g]   = valid ? mono_bits(o) : 0u;

        float mx = fmaxf(fmaxf(x1c, y1c), fmaxf(x2c, y2c));
        atomicMax(&g_maxc[img], __float_as_int(mx));
    }
}

// ================= Kernel 2: suppression matrix fill (all SMs) =============
__device__ __forceinline__ bool pair_sup(float4 bi, float ai,
                                         const float4* sbox, const float* sar,
                                         int j, int i, int k) {
    if (j <= i || j >= k) return false;
    float4 bj = sbox[j];
    float lx = fmaxf(bi.x, bj.x), ly = fmaxf(bi.y, bj.y);
    float rx = fminf(bi.z, bj.z), ry = fminf(bi.w, bj.w);
    float ww = fmaxf(__fsub_rn(rx, lx), 0.0f);
    float hh = fmaxf(__fsub_rn(ry, ly), 0.0f);
    float inter = __fmul_rn(ww, hh);
    if (!(inter > 0.0f)) return false;                 // ref: 0/denom=0 or 0/0=NaN -> false
    float denom = __fsub_rn(__fadd_rn(ai, sar[j]), inter);
    float hib = __fmul_rn(denom, 0.7000070f);
    float lob = __fmul_rn(denom, 0.6999930f);
    if (inter > hib && denom >= 0.0f) return true;     // certified > 0.7
    if (inter < lob) return false;                     // certified <= 0.7
    return __fdiv_rn(inter, denom) > NMS_T;            // exact boundary path
}

__device__ __forceinline__ void fill_row(int i, int k, int inst,
                                         const float4* sbox, const float* sar,
                                         int lane) {
    if (i >= k) return;
    float4 bi = sbox[i];
    float  ai = sar[i];
    unsigned long long* dst = &g_sup[(size_t)(inst * 1000 + i) * NW];
    unsigned mask = 0u;

    for (int w = i >> 6; w < NW; w++) {
        int j0 = w * 64 + lane;
        bool bA = pair_sup(bi, ai, sbox, sar, j0,      i, k);
        bool bB = pair_sup(bi, ai, sbox, sar, j0 + 32, i, k);
        unsigned m0 = __ballot_sync(0xffffffffu, bA);
        unsigned m1 = __ballot_sync(0xffffffffu, bB);
        unsigned long long wv = (unsigned long long)m0 | ((unsigned long long)m1 << 32);
        if (wv) {
            mask |= 1u << w;
            if (lane == 0) dst[w] = wv;          // write only nonzero words
        }
    }
    if (lane == 0) g_rowmask[inst * 1000 + i] = mask;
}

__global__ void __launch_bounds__(1024)
nms_fill_kernel() {
    const int bid  = blockIdx.x;
    const int inst = bid / FILL_RB;            // img*NLEV + lev
    const int rb   = bid % FILL_RB;
    const int img  = inst / NLEV, lev = inst % NLEV;
    const int k = c_k[lev], soff = c_soff[lev];
    if (rb * 64 >= k) return;
    const int base = img * K_ALL + soff;

    __shared__ float4 sbox[1000];
    __shared__ float  sar [1000];

    float maxc = __int_as_float(g_maxc[img]);
    float off  = __fmul_rn((float)lev, __fadd_rn(maxc, 1.0f));

    for (int j = threadIdx.x; j < k; j += 1024) {
        float4 b = g_boxv[base + j];
        float x1 = __fadd_rn(b.x, off), y1 = __fadd_rn(b.y, off);
        float x2 = __fadd_rn(b.z, off), y2 = __fadd_rn(b.w, off);
        sbox[j] = make_float4(x1, y1, x2, y2);
        sar[j]  = __fmul_rn(__fsub_rn(x2, x1), __fsub_rn(y2, y1));
    }
    __syncthreads();

    const int warp = threadIdx.x >> 5, lane = threadIdx.x & 31;
    fill_row(rb * 64 + warp,      k, inst, sbox, sar, lane);
    fill_row(rb * 64 + warp + 32, k, inst, sbox, sar, lane);
}

// ================= Kernel 3: lean chunk-parallel greedy scan ================
// 16 chunks of 64. Serial part: block-diagonal resolve (thread 0, smem-staged
// diagonal words, dmask-guided set-bit gather). Parallel part: warp q owns
// keep-word q; off-diagonal suppression words register-prefetched from L2 one
// chunk ahead; OR-combined with REDUX (__reduce_or_sync); lane 0 writes.
// Boolean-identical to sequential greedy NMS.
__global__ void __launch_bounds__(512, 1)
nms_scan_kernel() {
    __shared__ unsigned           srm[1024];     // rowmask per row
    __shared__ unsigned long long sdiagw[1024];  // diagonal word per row
    __shared__ unsigned long long skeep[NW], sdmask[NW];
    __shared__ unsigned sv[32], sd[32];
    __shared__ unsigned long long s_alive;

    const int inst = blockIdx.x;
    const int img = inst / NLEV, lev = inst % NLEV;
    const int k = c_k[lev], soff = c_soff[lev];
    const int base = img * K_ALL + soff;
    const int t = threadIdx.x;
    const int lane = t & 31, wid = t >> 5;

    // ---- phase A: stage diagonal words + rowmasks; ballots ----
    #pragma unroll
    for (int h = 0; h < 2; h++) {
        int r = t + h * 512;
        bool valid = false, dact = false;
        unsigned m = 0;
        if (r < k) {
            valid = (g_keyv[base + r] != 0u);
            m = g_rowmask[inst * 1000 + r];
            dact = (m >> (r >> 6)) & 1u;
        }
        srm[r] = m;
        sdiagw[r] = dact ? g_sup[(size_t)(inst * 1000 + r) * NW + (r >> 6)] : 0ULL;
        unsigned bv = __ballot_sync(0xffffffffu, valid);
        unsigned bd = __ballot_sync(0xffffffffu, dact);
        if (lane == 0) { sv[h * 16 + wid] = bv; sd[h * 16 + wid] = bd; }
    }
    __syncthreads();
    if (t < NW) {
        skeep[t]  = (unsigned long long)sv[2 * t] | ((unsigned long long)sv[2 * t + 1] << 32);
        sdmask[t] = (unsigned long long)sd[2 * t] | ((unsigned long long)sd[2 * t + 1] << 32);
    }
    __syncthreads();

    // ---- chunk loop ----
    const int NCH = (k + 63) >> 6;

    // prefetch chunk 0's words for this warp's output word (wid)
    unsigned long long p0 = 0, p1 = 0;
    if (wid > 0) {
        int r0 = lane, r1 = lane + 32;
        if (r0 < k && ((srm[r0] >> wid) & 1u))
            p0 = g_sup[(size_t)(inst * 1000 + r0) * NW + wid];
        if (r1 < k && ((srm[r1] >> wid) & 1u))
            p1 = g_sup[(size_t)(inst * 1000 + r1) * NW + wid];
    }

    for (int c = 0; c < NCH; c++) {
        // --- diagonal resolve (thread 0) ---
        if (t == 0) {
            unsigned long long alive = skeep[c];
            unsigned long long dm = sdmask[c];
            while (dm) {
                int bidx[8]; unsigned long long rw[8]; int cnt = 0;
                #pragma unroll
                for (int e = 0; e < 8; e++) {
                    if (!dm) break;
                    int b = __ffsll((long long)dm) - 1;
                    dm &= dm - 1ULL;
                    bidx[cnt] = b;
                    rw[cnt] = sdiagw[c * 64 + b];   // independent LDS, batched
                    cnt++;
                }
                for (int e = 0; e < cnt; e++)
                    if ((alive >> bidx[e]) & 1ULL) alive &= ~rw[e];
            }
            skeep[c] = alive;
            s_alive = alive;
        }
        __syncthreads();
        const unsigned long long alive = s_alive;

        // --- apply prefetched chunk-c words to keep-word wid ---
        unsigned long long v = 0;
        if (wid > c) {
            if ((alive >> lane) & 1ULL)        v  = p0;
            if ((alive >> (lane + 32)) & 1ULL) v |= p1;
        }

        // --- prefetch chunk c+1 (latency hidden behind redux + barrier + diag) ---
        p0 = p1 = 0;
        int cn = c + 1;
        if (cn < NCH && wid > cn) {
            int r0 = cn * 64 + lane, r1 = r0 + 32;
            if (r0 < k && ((srm[r0] >> wid) & 1u))
                p0 = g_sup[(size_t)(inst * 1000 + r0) * NW + wid];
            if (r1 < k && ((srm[r1] >> wid) & 1u))
                p1 = g_sup[(size_t)(inst * 1000 + r1) * NW + wid];
        }

        unsigned lo = __reduce_or_sync(0xffffffffu, (unsigned)v);
        unsigned hi = __reduce_or_sync(0xffffffffu, (unsigned)(v >> 32));
        if (lane == 0) {
            unsigned long long vv = ((unsigned long long)hi << 32) | lo;
            if (vv) skeep[wid] &= ~vv;     // one warp per word: no atomic needed
        }
        __syncthreads();
    }

    if (t < NW) g_keepbits[inst * NW + t] = skeep[t];
}

// ================= Kernel 4: rank kept candidates via 5-way merge ===========
__global__ void __launch_bounds__(1024, 1)
final_kernel(float* __restrict__ out) {
    __shared__ unsigned long long klist[K_ALL];
    __shared__ int lvbase[NLEV + 1];
    __shared__ int warpsum[32];

    const int img = blockIdx.x;
    const int t = threadIdx.x;
    const int wid = t >> 5, lane = t & 31;

    for (int x = t; x < POST_N * 4; x += 1024) out[img * POST_N * 4 + x] = 0.0f;
    for (int x = t; x < POST_N; x += 1024) out[BATCH * POST_N * 4 + img * POST_N + x] = 0.0f;
    if (t == 0) { lvbase[0] = 0; g_maxc[img] = 0; }   // re-zero maxc for next replay
    __syncthreads();

    for (int lev = 0; lev < NLEV; lev++) {
        const int k = c_k[lev], soff = c_soff[lev];
        bool kept = false;
        unsigned long long key = 0ULL;
        if (t < k) {
            unsigned long long kb = g_keepbits[(img * NLEV + lev) * NW + (t >> 6)];
            if ((kb >> (t & 63)) & 1ULL) {
                int slot = soff + t;
                kept = true;
                key = ((unsigned long long)g_keyv[img * K_ALL + slot] << 32) |
                      (unsigned)(~(unsigned)slot);
            }
        }
        unsigned bm = __ballot_sync(0xffffffffu, kept);
        if (lane == 0) warpsum[wid] = __popc(bm);
        __syncthreads();
        if (t < 32) {
            int v = warpsum[t];
            for (int d = 1; d < 32; d <<= 1) {
                int o = __shfl_up_sync(0xffffffffu, v, d);
                if (t >= d) v += o;
            }
            warpsum[t] = v;   // inclusive
            if (t == 31) lvbase[lev + 1] = lvbase[lev] + v;
        }
        __syncthreads();
        if (kept) {
            int pos = lvbase[lev] + (wid ? warpsum[wid - 1] : 0) +
                      __popc(bm & ((1u << lane) - 1u));
            klist[pos] = key;
        }
        __syncthreads();
    }

    const int C = lvbase[NLEV];
    for (int c = t; c < C; c += 1024) {
        int lev = 0;
        while (lev < NLEV - 1 && c >= lvbase[lev + 1]) lev++;
        unsigned long long key = klist[c];
        int rank = c - lvbase[lev];
        for (int l2 = 0; l2 < NLEV; l2++) {
            if (l2 == lev) continue;
            int lo = lvbase[l2], hi = lvbase[l2 + 1];
            while (lo < hi) {
                int mid = (lo + hi) >> 1;
                if (klist[mid] > key) lo = mid + 1; else hi = mid;
            }
            rank += lo - lvbase[l2];
        }
        if (rank < POST_N) {
            int slot = (int)(~(unsigned)key);
            float4 b = g_boxv[img * K_ALL + slot];
            float sc = g_scorev[img * K_ALL + slot];
            float* ob = out + (size_t)(img * POST_N + rank) * 4;
            ob[0] = b.x; ob[1] = b.y; ob[2] = b.z; ob[3] = b.w;
            out[BATCH * POST_N * 4 + img * POST_N + rank] = sc;
        }
    }
}

// ================= launch ====================
extern "C" void kernel_launch(void* const* d_in, const int* in_sizes, int n_in,
                              void* d_out, int out_size) {
    const float*  obj     = (const float*) d_in[0];   // [4, 159882]
    const float4* deltas  = (const float4*)d_in[1];   // [4, 159882, 4]
    const float4* anchors = (const float4*)d_in[2];   // [159882, 4]
    float* out = (float*)d_out;                       // boxes[4,1000,4] ++ scores[4,1000]

    cudaFuncSetAttribute(select_kernel, cudaFuncAttributeMaxDynamicSharedMemorySize, 98304);

    const int nelem = BATCH * A_TOTAL;                // 639528, divisible by 4
    hist_kernel<<<(nelem / 4 + 255) / 256, 256>>>(obj);
    select_kernel<<<NINST, 1024, 98304>>>(obj, deltas, anchors);
    nms_fill_kernel<<<NINST * FILL_RB, 1024>>>();
    nms_scan_kernel<<<NINST, 512>>>();
    final_kernel<<<BATCH, 1024>>>(out);
}

// round 14
// speedup vs baseline: 1.4884x; 1.0716x over previous
#include <cuda_runtime.h>
#include <math.h>

// ---------------- static configuration ----------------
#define BATCH   4
#define A_TOTAL 159882
#define NLEV    5
#define K_ALL   4507
#define POST_N  1000
#define IMG_WF  800.0f
#define IMG_HF  800.0f
#define MIN_SZ  0.001f
#define NMS_T   0.7f
#define BBOX_CLIP 4.135166556742356f
#define FILL_RB 16           // row-blocks of 64 rows (2 per warp) per (img,lev)
#define NW      16           // 64-bit words per suppression row (ceil(1000/64))
#define NINST   (BATCH * NLEV)

__constant__ int c_n[NLEV]    = {120000, 30000, 7500, 1875, 507};
__constant__ int c_off[NLEV]  = {0, 120000, 150000, 157500, 159375};
__constant__ int c_k[NLEV]    = {1000, 1000, 1000, 1000, 507};
__constant__ int c_soff[NLEV] = {0, 1000, 2000, 3000, 4000};

// ---------------- scratch (device globals; zero-init at load) --------------
__device__ unsigned           g_hist  [NINST * 4096];
__device__ float4             g_boxv  [BATCH * K_ALL];   // clipped boxes
__device__ float              g_scorev[BATCH * K_ALL];   // sigmoid scores
__device__ unsigned           g_keyv  [BATCH * K_ALL];   // mono(obj) if valid else 0
__device__ int                g_maxc  [BATCH];           // float bits (coords >= 0)
__device__ unsigned long long g_sup   [NINST * 1000 * NW];
__device__ unsigned           g_rowmask[NINST * 1000];   // nonzero-word mask per row
__device__ unsigned long long g_keepbits[NINST * NW];
__device__ int                g_fillcnt[NINST];          // last-block counter

__device__ __forceinline__ unsigned mono_bits(float f) {
    unsigned u = __float_as_uint(f);
    return (u & 0x80000000u) ? ~u : (u | 0x80000000u);
}

// in-shared-memory bitonic sort, descending, m = power of 2
__device__ __forceinline__ void bitonic_desc(unsigned long long* keys, int m, int t, int NT) {
    for (int k = 2; k <= m; k <<= 1) {
        for (int j = k >> 1; j > 0; j >>= 1) {
            for (int i = t; i < m; i += NT) {
                int ix = i ^ j;
                if (ix > i) {
                    unsigned long long a = keys[i], b = keys[ix];
                    bool desc = ((i & k) == 0);
                    if (desc ? (a < b) : (a > b)) { keys[i] = b; keys[ix] = a; }
                }
            }
            __syncthreads();
        }
    }
}

extern __shared__ unsigned char dynsm[];

// ================= Kernel 0: flat histogram (float4 loads, global RED) =====
__global__ void __launch_bounds__(256)
hist_kernel(const float* __restrict__ obj) {
    int idx = blockIdx.x * 256 + threadIdx.x;          // one float4 per thread
    if (idx * 4 >= BATCH * A_TOTAL) return;
    float4 f = ((const float4*)obj)[idx];
    float vals[4] = {f.x, f.y, f.z, f.w};
    int g0 = idx * 4;
    #pragma unroll
    for (int e = 0; e < 4; e++) {
        int g = g0 + e;
        int img = g / A_TOTAL;
        int r = g - img * A_TOTAL;
        int lev = (r < 120000) ? 0 : (r < 150000) ? 1 : (r < 157500) ? 2 :
                  (r < 159375) ? 3 : 4;
        unsigned u = mono_bits(vals[e]);
        atomicAdd(&g_hist[(img * NLEV + lev) * 4096 + (u >> 20)], 1u);
    }
}

// ================= Kernel 1: select + compact + sort + inline decode =======
__global__ void __launch_bounds__(1024, 1)
select_kernel(const float* __restrict__ obj,
              const float4* __restrict__ deltas,
              const float4* __restrict__ anchors) {
    unsigned long long* cand = (unsigned long long*)dynsm;            // 8192 (64KB)
    unsigned*           hist = (unsigned*)(dynsm + 65536);            // 4096 (16KB)
    int*                sA   = (int*)(dynsm + 65536 + 16384);         // 1024
    int*                sB   = sA + 1024;                             // 1024
    __shared__ int sh_B, sh_cnt;

    const int inst = blockIdx.x;           // 0..19
    const int img = inst / NLEV;
    const int lev = inst % NLEV;
    const int n = c_n[lev], lvoff = c_off[lev], k = c_k[lev], soff = c_soff[lev];
    const int start = img * A_TOTAL + lvoff;
    const float* __restrict__ src = obj + start;
    const int t = threadIdx.x, NT = blockDim.x;

    for (int b = t; b < 4096; b += NT) {
        hist[b] = g_hist[inst * 4096 + b];
        g_hist[inst * 4096 + b] = 0u;       // re-zero for next replay
    }
    __syncthreads();

    // segment sums (4 buckets each) + parallel suffix-inclusive scan
    {
        int base = t * 4;
        sA[t] = (int)(hist[base] + hist[base + 1] + hist[base + 2] + hist[base + 3]);
    }
    __syncthreads();
    {
        int* pin = sA; int* pout = sB;
        for (int d = 1; d < 1024; d <<= 1) {
            int v = pin[t];
            if (t + d < 1024) v += pin[t + d];
            pout[t] = v;
            __syncthreads();
            int* tmp = pin; pin = pout; pout = tmp;
        }
        int suffIncl  = pin[t];
        int suffAfter = (t < 1023) ? pin[t + 1] : 0;
        if (suffIncl >= k && suffAfter < k) {
            int cum = suffAfter, B = 4 * t;
            for (int bb = 4 * t + 3; bb >= 4 * t; bb--) {
                if (cum + (int)hist[bb] >= k) { B = bb; break; }
                cum += (int)hist[bb];
            }
            sh_B = B;
            sh_cnt = 0;
        }
    }
    __syncthreads();

    const int B = sh_B;
    // compaction: alignment prologue + float4 body + scalar tail
    #define TESTC(val, jj) do {                                              \
        unsigned u_ = mono_bits(val);                                        \
        if ((int)(u_ >> 20) >= B) {                                          \
            int p_ = atomicAdd(&sh_cnt, 1);                                  \
            if (p_ < 8192)                                                   \
                cand[p_] = ((unsigned long long)u_ << 32) |                  \
                           (unsigned)(~(unsigned)(jj));                      \
        }                                                                    \
    } while (0)
    {
        int a0 = (4 - (start & 3)) & 3;
        if (a0 > n) a0 = n;
        for (int j = t; j < a0; j += NT) TESTC(src[j], j);
        const int nv = (n - a0) >> 2;
        const float4* src4 = (const float4*)(src + a0);
        for (int v = t; v < nv; v += NT) {
            float4 f = src4[v];
            int j = a0 + v * 4;
            TESTC(f.x, j); TESTC(f.y, j + 1); TESTC(f.z, j + 2); TESTC(f.w, j + 3);
        }
        for (int j = a0 + (nv << 2) + t; j < n; j += NT) TESTC(src[j], j);
    }
    #undef TESTC
    __syncthreads();

    int cnt = sh_cnt;
    if (cnt > 8192) cnt = 8192;
    int m = 1;
    while (m < cnt || m < k) m <<= 1;
    if (m > 8192) m = 8192;
    for (int i = cnt + t; i < m; i += NT) cand[i] = 0ULL;
    __syncthreads();

    bitonic_desc(cand, m, t, NT);

    // inline decode of the k selected candidates
    for (int s = t; s < k; s += NT) {
        int j = (int)(~(unsigned)cand[s]);     // local index (ties asc = lax.top_k)
        int idx = lvoff + j;
        int g = img * K_ALL + soff + s;

        float  o = obj[img * A_TOTAL + idx];
        float4 d = deltas[img * A_TOTAL + idx];
        float4 a = anchors[idx];

        float wa  = __fsub_rn(a.z, a.x);
        float ha  = __fsub_rn(a.w, a.y);
        float cxa = __fadd_rn(a.x, __fmul_rn(0.5f, wa));
        float cya = __fadd_rn(a.y, __fmul_rn(0.5f, ha));
        float dw  = fminf(d.z, BBOX_CLIP);
        float dh  = fminf(d.w, BBOX_CLIP);
        float cx  = __fadd_rn(__fmul_rn(d.x, wa), cxa);
        float cy  = __fadd_rn(__fmul_rn(d.y, ha), cya);
        float w   = __fmul_rn(expf(dw), wa);
        float h   = __fmul_rn(expf(dh), ha);
        float x1  = __fsub_rn(cx, __fmul_rn(0.5f, w));
        float y1  = __fsub_rn(cy, __fmul_rn(0.5f, h));
        float x2  = __fadd_rn(cx, __fmul_rn(0.5f, w));
        float y2  = __fadd_rn(cy, __fmul_rn(0.5f, h));

        float x1c = fminf(fmaxf(x1, 0.0f), IMG_WF);
        float y1c = fminf(fmaxf(y1, 0.0f), IMG_HF);
        float x2c = fminf(fmaxf(x2, 0.0f), IMG_WF);
        float y2c = fminf(fmaxf(y2, 0.0f), IMG_HF);

        float score = 1.0f / (1.0f + expf(-o));
        bool valid = (__fsub_rn(x2c, x1c) >= MIN_SZ) &&
                     (__fsub_rn(y2c, y1c) >= MIN_SZ) &&
                     (score >= 0.0f);

        g_boxv[g]   = make_float4(x1c, y1c, x2c, y2c);
        g_scorev[g] = score;
        g_keyv[g]   = valid ? mono_bits(o) : 0u;

        float mx = fmaxf(fmaxf(x1c, y1c), fmaxf(x2c, y2c));
        atomicMax(&g_maxc[img], __float_as_int(mx));
    }
}

// ================= Kernel 2: fused fill + (last block) scan ================
__device__ __forceinline__ bool pair_sup(float4 bi, float ai,
                                         const float4* sbox, const float* sar,
                                         int j, int i, int k) {
    if (j <= i || j >= k) return false;
    float4 bj = sbox[j];
    float lx = fmaxf(bi.x, bj.x), ly = fmaxf(bi.y, bj.y);
    float rx = fminf(bi.z, bj.z), ry = fminf(bi.w, bj.w);
    float ww = fmaxf(__fsub_rn(rx, lx), 0.0f);
    float hh = fmaxf(__fsub_rn(ry, ly), 0.0f);
    float inter = __fmul_rn(ww, hh);
    if (!(inter > 0.0f)) return false;                 // ref: 0/denom=0 or 0/0=NaN -> false
    float denom = __fsub_rn(__fadd_rn(ai, sar[j]), inter);
    float hib = __fmul_rn(denom, 0.7000070f);
    float lob = __fmul_rn(denom, 0.6999930f);
    if (inter > hib && denom >= 0.0f) return true;     // certified > 0.7
    if (inter < lob) return false;                     // certified <= 0.7
    return __fdiv_rn(inter, denom) > NMS_T;            // exact boundary path
}

__device__ __forceinline__ void fill_row(int i, int k, int inst,
                                         const float4* sbox, const float* sar,
                                         int lane) {
    if (i >= k) return;                    // warp-uniform (i per warp)
    float4 bi = sbox[i];
    float  ai = sar[i];
    unsigned long long* dst = &g_sup[(size_t)(inst * 1000 + i) * NW];
    unsigned mask = 0u;

    for (int w = i >> 6; w < NW; w++) {
        int j0 = w * 64 + lane;
        bool bA = pair_sup(bi, ai, sbox, sar, j0,      i, k);
        bool bB = pair_sup(bi, ai, sbox, sar, j0 + 32, i, k);
        unsigned m0 = __ballot_sync(0xffffffffu, bA);
        unsigned m1 = __ballot_sync(0xffffffffu, bB);
        unsigned long long wv = (unsigned long long)m0 | ((unsigned long long)m1 << 32);
        if (wv) {
            mask |= 1u << w;
            if (lane == 0) dst[w] = wv;          // write only nonzero words
        }
    }
    if (lane == 0) g_rowmask[inst * 1000 + i] = mask;
}

__global__ void __launch_bounds__(1024, 1)
fillscan_kernel() {
    __shared__ float4 sbox[1000];
    __shared__ float  sar [1000];
    // scan-phase shared state
    __shared__ unsigned           srm[1024];
    __shared__ unsigned long long sdiagw[1024];
    __shared__ unsigned long long skeep[NW], sdmask[NW];
    __shared__ unsigned sv[32], sd[32];
    __shared__ unsigned long long s_alive;
    __shared__ int s_last;

    const int bid  = blockIdx.x;
    const int inst = bid / FILL_RB;            // img*NLEV + lev
    const int rb   = bid % FILL_RB;
    const int img  = inst / NLEV, lev = inst % NLEV;
    const int k = c_k[lev], soff = c_soff[lev];
    const int base = img * K_ALL + soff;
    const int t = threadIdx.x;
    const int lane = t & 31, wid = t >> 5;

    const bool haswork = (rb * 64 < k);
    if (haswork) {
        float maxc = __int_as_float(g_maxc[img]);
        float off  = __fmul_rn((float)lev, __fadd_rn(maxc, 1.0f));
        for (int j = t; j < k; j += 1024) {
            float4 b = g_boxv[base + j];
            float x1 = __fadd_rn(b.x, off), y1 = __fadd_rn(b.y, off);
            float x2 = __fadd_rn(b.z, off), y2 = __fadd_rn(b.w, off);
            sbox[j] = make_float4(x1, y1, x2, y2);
            sar[j]  = __fmul_rn(__fsub_rn(x2, x1), __fsub_rn(y2, y1));
        }
        __syncthreads();
        fill_row(rb * 64 + wid,      k, inst, sbox, sar, lane);
        fill_row(rb * 64 + wid + 32, k, inst, sbox, sar, lane);
    }

    // ---- last-block handoff ----
    __threadfence();
    __syncthreads();
    if (t == 0) s_last = (atomicAdd(&g_fillcnt[inst], 1) == FILL_RB - 1) ? 1 : 0;
    __syncthreads();
    if (!s_last) return;
    if (t == 0) g_fillcnt[inst] = 0;           // reset for next replay

    // ================= scan phase (this block only) =================
    // phase A: stage diagonal words + rowmasks; ballots
    {
        int r = t;
        bool valid = false, dact = false;
        unsigned m = 0;
        if (r < k) {
            valid = (g_keyv[base + r] != 0u);
            m = g_rowmask[inst * 1000 + r];
            dact = (m >> (r >> 6)) & 1u;
        }
        srm[r] = m;
        sdiagw[r] = dact ? g_sup[(size_t)(inst * 1000 + r) * NW + (r >> 6)] : 0ULL;
        unsigned bv = __ballot_sync(0xffffffffu, valid);
        unsigned bd = __ballot_sync(0xffffffffu, dact);
        if (lane == 0) { sv[wid] = bv; sd[wid] = bd; }
    }
    __syncthreads();
    if (t < NW) {
        skeep[t]  = (unsigned long long)sv[2 * t] | ((unsigned long long)sv[2 * t + 1] << 32);
        sdmask[t] = (unsigned long long)sd[2 * t] | ((unsigned long long)sd[2 * t + 1] << 32);
    }
    __syncthreads();

    const int NCH = (k + 63) >> 6;

    // prefetch chunk 0's words for this warp's output word (wid)
    unsigned long long p0 = 0, p1 = 0;
    if (wid > 0 && wid < NW) {
        int r0 = lane, r1 = lane + 32;
        if (r0 < k && ((srm[r0] >> wid) & 1u))
            p0 = g_sup[(size_t)(inst * 1000 + r0) * NW + wid];
        if (r1 < k && ((srm[r1] >> wid) & 1u))
            p1 = g_sup[(size_t)(inst * 1000 + r1) * NW + wid];
    }

    for (int c = 0; c < NCH; c++) {
        // --- diagonal resolve (thread 0) ---
        if (t == 0) {
            unsigned long long alive = skeep[c];
            unsigned long long dm = sdmask[c];
            while (dm) {
                int bidx[8]; unsigned long long rw[8]; int cnt = 0;
                #pragma unroll
                for (int e = 0; e < 8; e++) {
                    if (!dm) break;
                    int b = __ffsll((long long)dm) - 1;
                    dm &= dm - 1ULL;
                    bidx[cnt] = b;
                    rw[cnt] = sdiagw[c * 64 + b];   // independent LDS, batched
                    cnt++;
                }
                for (int e = 0; e < cnt; e++)
                    if ((alive >> bidx[e]) & 1ULL) alive &= ~rw[e];
            }
            skeep[c] = alive;
            s_alive = alive;
        }
        __syncthreads();
        const unsigned long long alive = s_alive;

        if (wid < NW) {
            // apply prefetched chunk-c words to keep-word wid
            unsigned long long v = 0;
            if (wid > c) {
                if ((alive >> lane) & 1ULL)        v  = p0;
                if ((alive >> (lane + 32)) & 1ULL) v |= p1;
            }

            // prefetch chunk c+1
            p0 = p1 = 0;
            int cn = c + 1;
            if (cn < NCH && wid > cn) {
                int r0 = cn * 64 + lane, r1 = r0 + 32;
                if (r0 < k && ((srm[r0] >> wid) & 1u))
                    p0 = g_sup[(size_t)(inst * 1000 + r0) * NW + wid];
                if (r1 < k && ((srm[r1] >> wid) & 1u))
                    p1 = g_sup[(size_t)(inst * 1000 + r1) * NW + wid];
            }

            unsigned lo = __reduce_or_sync(0xffffffffu, (unsigned)v);
            unsigned hi = __reduce_or_sync(0xffffffffu, (unsigned)(v >> 32));
            if (lane == 0) {
                unsigned long long vv = ((unsigned long long)hi << 32) | lo;
                if (vv) skeep[wid] &= ~vv;     // one warp per word: no race
            }
        }
        __syncthreads();
    }

    if (t < NW) g_keepbits[inst * NW + t] = skeep[t];
}

// ================= Kernel 3: rank kept candidates via 5-way merge ===========
__global__ void __launch_bounds__(1024, 1)
final_kernel(float* __restrict__ out) {
    __shared__ unsigned long long klist[K_ALL];
    __shared__ int lvbase[NLEV + 1];
    __shared__ int warpsum[32];

    const int img = blockIdx.x;
    const int t = threadIdx.x;
    const int wid = t >> 5, lane = t & 31;

    for (int x = t; x < POST_N * 4; x += 1024) out[img * POST_N * 4 + x] = 0.0f;
    for (int x = t; x < POST_N; x += 1024) out[BATCH * POST_N * 4 + img * POST_N + x] = 0.0f;
    if (t == 0) { lvbase[0] = 0; g_maxc[img] = 0; }   // re-zero maxc for next replay
    __syncthreads();

    for (int lev = 0; lev < NLEV; lev++) {
        const int k = c_k[lev], soff = c_soff[lev];
        bool kept = false;
        unsigned long long key = 0ULL;
        if (t < k) {
            unsigned long long kb = g_keepbits[(img * NLEV + lev) * NW + (t >> 6)];
            if ((kb >> (t & 63)) & 1ULL) {
                int slot = soff + t;
                kept = true;
                key = ((unsigned long long)g_keyv[img * K_ALL + slot] << 32) |
                      (unsigned)(~(unsigned)slot);
            }
        }
        unsigned bm = __ballot_sync(0xffffffffu, kept);
        if (lane == 0) warpsum[wid] = __popc(bm);
        __syncthreads();
        if (t < 32) {
            int v = warpsum[t];
            for (int d = 1; d < 32; d <<= 1) {
                int o = __shfl_up_sync(0xffffffffu, v, d);
                if (t >= d) v += o;
            }
            warpsum[t] = v;   // inclusive
            if (t == 31) lvbase[lev + 1] = lvbase[lev] + v;
        }
        __syncthreads();
        if (kept) {
            int pos = lvbase[lev] + (wid ? warpsum[wid - 1] : 0) +
                      __popc(bm & ((1u << lane) - 1u));
            klist[pos] = key;
        }
        __syncthreads();
    }

    const int C = lvbase[NLEV];
    for (int c = t; c < C; c += 1024) {
        int lev = 0;
        while (lev < NLEV - 1 && c >= lvbase[lev + 1]) lev++;
        unsigned long long key = klist[c];
        int rank = c - lvbase[lev];
        for (int l2 = 0; l2 < NLEV; l2++) {
            if (l2 == lev) continue;
            int lo = lvbase[l2], hi = lvbase[l2 + 1];
            while (lo < hi) {
                int mid = (lo + hi) >> 1;
                if (klist[mid] > key) lo = mid + 1; else hi = mid;
            }
            rank += lo - lvbase[l2];
        }
        if (rank < POST_N) {
            int slot = (int)(~(unsigned)key);
            float4 b = g_boxv[img * K_ALL + slot];
            float sc = g_scorev[img * K_ALL + slot];
            float* ob = out + (size_t)(img * POST_N + rank) * 4;
            ob[0] = b.x; ob[1] = b.y; ob[2] = b.z; ob[3] = b.w;
            out[BATCH * POST_N * 4 + img * POST_N + rank] = sc;
        }
    }
}

// ================= launch ====================
extern "C" void kernel_launch(void* const* d_in, const int* in_sizes, int n_in,
                              void* d_out, int out_size) {
    const float*  obj     = (const float*) d_in[0];   // [4, 159882]
    const float4* deltas  = (const float4*)d_in[1];   // [4, 159882, 4]
    const float4* anchors = (const float4*)d_in[2];   // [159882, 4]
    float* out = (float*)d_out;                       // boxes[4,1000,4] ++ scores[4,1000]

    cudaFuncSetAttribute(select_kernel, cudaFuncAttributeMaxDynamicSharedMemorySize, 98304);

    const int nelem = BATCH * A_TOTAL;                // 639528 = 4 * 159882
    hist_kernel<<<(nelem / 4 + 255) / 256, 256>>>(obj);
    select_kernel<<<NINST, 1024, 98304>>>(obj, deltas, anchors);
    fillscan_kernel<<<NINST * FILL_RB, 1024>>>();
    final_kernel<<<BATCH, 1024>>>(out);
}

// round 15
// speedup vs baseline: 1.5510x; 1.0420x over previous
#include <cuda_runtime.h>
#include <math.h>

// ---------------- static configuration ----------------
#define BATCH   4
#define A_TOTAL 159882
#define NLEV    5
#define K_ALL   4507
#define POST_N  1000
#define IMG_WF  800.0f
#define IMG_HF  800.0f
#define MIN_SZ  0.001f
#define NMS_T   0.7f
#define BBOX_CLIP 4.135166556742356f
#define FILL_RB 16           // row-blocks of 64 rows (2 per warp) per (img,lev)
#define NW      16           // 64-bit words per suppression row (ceil(1000/64))
#define NINST   (BATCH * NLEV)

__constant__ int c_n[NLEV]    = {120000, 30000, 7500, 1875, 507};
__constant__ int c_off[NLEV]  = {0, 120000, 150000, 157500, 159375};
__constant__ int c_k[NLEV]    = {1000, 1000, 1000, 1000, 507};
__constant__ int c_soff[NLEV] = {0, 1000, 2000, 3000, 4000};

// ---------------- scratch (device globals; zero-init at load) --------------
__device__ unsigned           g_hist  [NINST * 4096];
__device__ float4             g_boxv  [BATCH * K_ALL];   // clipped boxes
__device__ float              g_scorev[BATCH * K_ALL];   // sigmoid scores
__device__ unsigned           g_keyv  [BATCH * K_ALL];   // mono(obj) if valid else 0
__device__ int                g_maxc  [BATCH];           // float bits (coords >= 0)
__device__ unsigned long long g_sup   [NINST * 1000 * NW];
__device__ unsigned           g_rowmask[NINST * 1000];   // nonzero-word mask per row
__device__ unsigned long long g_keepbits[NINST * NW];
__device__ int                g_fillcnt[NINST];          // last-block counter

__device__ __forceinline__ unsigned mono_bits(float f) {
    unsigned u = __float_as_uint(f);
    return (u & 0x80000000u) ? ~u : (u | 0x80000000u);
}

extern __shared__ unsigned char dynsm[];

// ================= Kernel 0: flat histogram (float4 loads, global RED) =====
__global__ void __launch_bounds__(256)
hist_kernel(const float* __restrict__ obj) {
    int idx = blockIdx.x * 256 + threadIdx.x;          // one float4 per thread
    if (idx * 4 >= BATCH * A_TOTAL) return;
    float4 f = ((const float4*)obj)[idx];
    float vals[4] = {f.x, f.y, f.z, f.w};
    int g0 = idx * 4;
    #pragma unroll
    for (int e = 0; e < 4; e++) {
        int g = g0 + e;
        int img = g / A_TOTAL;
        int r = g - img * A_TOTAL;
        int lev = (r < 120000) ? 0 : (r < 150000) ? 1 : (r < 157500) ? 2 :
                  (r < 159375) ? 3 : 4;
        unsigned u = mono_bits(vals[e]);
        atomicAdd(&g_hist[(img * NLEV + lev) * 4096 + (u >> 20)], 1u);
    }
}

// suffix-scan threshold finder over a 4096-bin histogram (all threads call)
__device__ __forceinline__ int find_bucket(const unsigned* hist, int* sA, int* sB,
                                           int kneed, int t, int* shB) {
    sA[t] = (int)(hist[t * 4] + hist[t * 4 + 1] + hist[t * 4 + 2] + hist[t * 4 + 3]);
    __syncthreads();
    int* pin = sA; int* pout = sB;
    for (int d = 1; d < 1024; d <<= 1) {
        int v = pin[t];
        if (t + d < 1024) v += pin[t + d];
        pout[t] = v;
        __syncthreads();
        int* tmp = pin; pin = pout; pout = tmp;
    }
    int suffIncl  = pin[t];
    int suffAfter = (t < 1023) ? pin[t + 1] : 0;
    if (suffIncl >= kneed && suffAfter < kneed) {
        int cum = suffAfter, B = 4 * t;
        for (int bb = 4 * t + 3; bb >= 4 * t; bb--) {
            if (cum + (int)hist[bb] >= kneed) { B = bb; break; }
            cum += (int)hist[bb];
        }
        *shB = B;
    }
    __syncthreads();
    return *shB;
}

// decode one selected candidate into output slot s
__device__ __forceinline__ void decode_one(unsigned long long key, int s,
                                           int img, int lvoff, int soff,
                                           const float* __restrict__ obj,
                                           const float4* __restrict__ deltas,
                                           const float4* __restrict__ anchors) {
    int j = (int)(~(unsigned)key);
    int idx = lvoff + j;
    int g = img * K_ALL + soff + s;

    float  o = obj[img * A_TOTAL + idx];
    float4 d = deltas[img * A_TOTAL + idx];
    float4 a = anchors[idx];

    float wa  = __fsub_rn(a.z, a.x);
    float ha  = __fsub_rn(a.w, a.y);
    float cxa = __fadd_rn(a.x, __fmul_rn(0.5f, wa));
    float cya = __fadd_rn(a.y, __fmul_rn(0.5f, ha));
    float dw  = fminf(d.z, BBOX_CLIP);
    float dh  = fminf(d.w, BBOX_CLIP);
    float cx  = __fadd_rn(__fmul_rn(d.x, wa), cxa);
    float cy  = __fadd_rn(__fmul_rn(d.y, ha), cya);
    float w   = __fmul_rn(expf(dw), wa);
    float h   = __fmul_rn(expf(dh), ha);
    float x1  = __fsub_rn(cx, __fmul_rn(0.5f, w));
    float y1  = __fsub_rn(cy, __fmul_rn(0.5f, h));
    float x2  = __fadd_rn(cx, __fmul_rn(0.5f, w));
    float y2  = __fadd_rn(cy, __fmul_rn(0.5f, h));

    float x1c = fminf(fmaxf(x1, 0.0f), IMG_WF);
    float y1c = fminf(fmaxf(y1, 0.0f), IMG_HF);
    float x2c = fminf(fmaxf(x2, 0.0f), IMG_WF);
    float y2c = fminf(fmaxf(y2, 0.0f), IMG_HF);

    float score = 1.0f / (1.0f + expf(-o));
    bool valid = (__fsub_rn(x2c, x1c) >= MIN_SZ) &&
                 (__fsub_rn(y2c, y1c) >= MIN_SZ) &&
                 (score >= 0.0f);

    g_boxv[g]   = make_float4(x1c, y1c, x2c, y2c);
    g_scorev[g] = score;
    g_keyv[g]   = valid ? mono_bits(o) : 0u;

    float mx = fmaxf(fmaxf(x1c, y1c), fmaxf(x2c, y2c));
    atomicMax(&g_maxc[img], __float_as_int(mx));
}

// ================= Kernel 1: select via 24-bit refine + counting rank ======
__global__ void __launch_bounds__(1024, 1)
select_kernel(const float* __restrict__ obj,
              const float4* __restrict__ deltas,
              const float4* __restrict__ anchors) {
    unsigned long long* cand = (unsigned long long*)dynsm;            // 8192 (64KB)
    unsigned*           hist = (unsigned*)(dynsm + 65536);            // 4096 (16KB, reused)
    int*                sA   = (int*)(dynsm + 81920);                 // 1024
    int*                sB   = (int*)(dynsm + 86016);                 // 1024
    unsigned long long* sel  = (unsigned long long*)(dynsm + 90112);  // 2048 (16KB)
    __shared__ int sh_B, sh_B2, sh_cnt, sh_above, sh_selcnt;

    const int inst = blockIdx.x;           // 0..19
    const int img = inst / NLEV;
    const int lev = inst % NLEV;
    const int n = c_n[lev], lvoff = c_off[lev], k = c_k[lev], soff = c_soff[lev];
    const int start = img * A_TOTAL + lvoff;
    const float* __restrict__ src = obj + start;
    const int t = threadIdx.x, NT = blockDim.x;

    if (t == 0) { sh_cnt = 0; sh_above = 0; sh_selcnt = 0; }
    for (int b = t; b < 4096; b += NT) {
        hist[b] = g_hist[inst * 4096 + b];
        g_hist[inst * 4096 + b] = 0u;       // re-zero for next replay
    }
    __syncthreads();

    const int B = find_bucket(hist, sA, sB, k, t, &sh_B);

    // compaction: alignment prologue + float4 body + scalar tail
    #define TESTC(val, jj) do {                                              \
        unsigned u_ = mono_bits(val);                                        \
        if ((int)(u_ >> 20) >= B) {                                          \
            int p_ = atomicAdd(&sh_cnt, 1);                                  \
            if (p_ < 8192)                                                   \
                cand[p_] = ((unsigned long long)u_ << 32) |                  \
                           (unsigned)(~(unsigned)(jj));                      \
        }                                                                    \
    } while (0)
    {
        int a0 = (4 - (start & 3)) & 3;
        if (a0 > n) a0 = n;
        for (int j = t; j < a0; j += NT) TESTC(src[j], j);
        const int nv = (n - a0) >> 2;
        const float4* src4 = (const float4*)(src + a0);
        for (int v = t; v < nv; v += NT) {
            float4 f = src4[v];
            int j = a0 + v * 4;
            TESTC(f.x, j); TESTC(f.y, j + 1); TESTC(f.z, j + 2); TESTC(f.w, j + 3);
        }
        for (int j = a0 + (nv << 2) + t; j < n; j += NT) TESTC(src[j], j);
    }
    #undef TESTC
    __syncthreads();

    const int cnt = (sh_cnt > 8192) ? 8192 : sh_cnt;

    // second-level histogram (key bits [19:8] -> bits [51:40] of composite)
    for (int b = t; b < 4096; b += NT) hist[b] = 0u;   // reuse as hist2
    __syncthreads();
    for (int i = t; i < cnt; i += NT) {
        unsigned long long key = cand[i];
        int top = (int)(key >> 52);
        if (top > B) atomicAdd(&sh_above, 1);
        else         atomicAdd(&hist[(unsigned)(key >> 40) & 0xfffu], 1u);
    }
    __syncthreads();

    const int kneed2 = k - sh_above;                    // in [1, k] by construction
    const int B2 = find_bucket(hist, sA, sB, kneed2, t, &sh_B2);

    // recompact: selected = (top > B) || (top == B && mid >= B2)
    for (int i = t; i < cnt; i += NT) {
        unsigned long long key = cand[i];
        int top = (int)(key >> 52);
        int mid = (int)((key >> 40) & 0xfffu);
        if (top > B || mid >= B2) {
            int p = atomicAdd(&sh_selcnt, 1);
            if (p < 2048) sel[p] = key;
        }
    }
    __syncthreads();

    const int m = (sh_selcnt > 2048) ? 2048 : sh_selcnt;

    // counting rank (rank = #greater); keys unique -> exact permutation
    unsigned long long k0 = (t < m) ? sel[t] : 0ULL;
    unsigned long long k1 = (t + 1024 < m) ? sel[t + 1024] : 0ULL;
    int r0 = 0, r1 = 0;
    if (m <= 1024) {
        for (int i = 0; i < m; i++) r0 += (sel[i] > k0);
    } else {
        for (int i = 0; i < m; i++) {
            unsigned long long v = sel[i];
            r0 += (v > k0); r1 += (v > k1);
        }
    }

    if (t < m && r0 < k)            decode_one(k0, r0, img, lvoff, soff, obj, deltas, anchors);
    if (t + 1024 < m && r1 < k)     decode_one(k1, r1, img, lvoff, soff, obj, deltas, anchors);
}

// ================= Kernel 2: fused fill + (last block) scan ================
__device__ __forceinline__ bool pair_sup(float4 bi, float ai,
                                         const float4* sbox, const float* sar,
                                         int j, int i, int k) {
    if (j <= i || j >= k) return false;
    float4 bj = sbox[j];
    float lx = fmaxf(bi.x, bj.x), ly = fmaxf(bi.y, bj.y);
    float rx = fminf(bi.z, bj.z), ry = fminf(bi.w, bj.w);
    float ww = fmaxf(__fsub_rn(rx, lx), 0.0f);
    float hh = fmaxf(__fsub_rn(ry, ly), 0.0f);
    float inter = __fmul_rn(ww, hh);
    if (!(inter > 0.0f)) return false;                 // ref: 0/denom=0 or 0/0=NaN -> false
    float denom = __fsub_rn(__fadd_rn(ai, sar[j]), inter);
    float hib = __fmul_rn(denom, 0.7000070f);
    float lob = __fmul_rn(denom, 0.6999930f);
    if (inter > hib && denom >= 0.0f) return true;     // certified > 0.7
    if (inter < lob) return false;                     // certified <= 0.7
    return __fdiv_rn(inter, denom) > NMS_T;            // exact boundary path
}

__device__ __forceinline__ void fill_row(int i, int k, int inst,
                                         const float4* sbox, const float* sar,
                                         int lane) {
    if (i >= k) return;                    // warp-uniform (i per warp)
    float4 bi = sbox[i];
    float  ai = sar[i];
    unsigned long long* dst = &g_sup[(size_t)(inst * 1000 + i) * NW];
    unsigned mask = 0u;

    for (int w = i >> 6; w < NW; w++) {
        int j0 = w * 64 + lane;
        bool bA = pair_sup(bi, ai, sbox, sar, j0,      i, k);
        bool bB = pair_sup(bi, ai, sbox, sar, j0 + 32, i, k);
        unsigned m0 = __ballot_sync(0xffffffffu, bA);
        unsigned m1 = __ballot_sync(0xffffffffu, bB);
        unsigned long long wv = (unsigned long long)m0 | ((unsigned long long)m1 << 32);
        if (wv) {
            mask |= 1u << w;
            if (lane == 0) dst[w] = wv;          // write only nonzero words
        }
    }
    if (lane == 0) g_rowmask[inst * 1000 + i] = mask;
}

__global__ void __launch_bounds__(1024, 1)
fillscan_kernel() {
    __shared__ float4 sbox[1000];
    __shared__ float  sar [1000];
    __shared__ unsigned           srm[1024];
    __shared__ unsigned long long sdiagw[1024];
    __shared__ unsigned long long skeep[NW], sdmask[NW];
    __shared__ unsigned sv[32], sd[32];
    __shared__ unsigned long long s_alive;
    __shared__ int s_last;

    const int bid  = blockIdx.x;
    const int inst = bid / FILL_RB;            // img*NLEV + lev
    const int rb   = bid % FILL_RB;
    const int img  = inst / NLEV, lev = inst % NLEV;
    const int k = c_k[lev], soff = c_soff[lev];
    const int base = img * K_ALL + soff;
    const int t = threadIdx.x;
    const int lane = t & 31, wid = t >> 5;

    const bool haswork = (rb * 64 < k);
    if (haswork) {
        float maxc = __int_as_float(g_maxc[img]);
        float off  = __fmul_rn((float)lev, __fadd_rn(maxc, 1.0f));
        for (int j = t; j < k; j += 1024) {
            float4 b = g_boxv[base + j];
            float x1 = __fadd_rn(b.x, off), y1 = __fadd_rn(b.y, off);
            float x2 = __fadd_rn(b.z, off), y2 = __fadd_rn(b.w, off);
            sbox[j] = make_float4(x1, y1, x2, y2);
            sar[j]  = __fmul_rn(__fsub_rn(x2, x1), __fsub_rn(y2, y1));
        }
        __syncthreads();
        fill_row(rb * 64 + wid,      k, inst, sbox, sar, lane);
        fill_row(rb * 64 + wid + 32, k, inst, sbox, sar, lane);
    }

    // ---- last-block handoff ----
    __threadfence();
    __syncthreads();
    if (t == 0) s_last = (atomicAdd(&g_fillcnt[inst], 1) == FILL_RB - 1) ? 1 : 0;
    __syncthreads();
    if (!s_last) return;
    if (t == 0) g_fillcnt[inst] = 0;           // reset for next replay

    // ================= scan phase (this block only) =================
    {
        int r = t;
        bool valid = false, dact = false;
        unsigned m = 0;
        if (r < k) {
            valid = (g_keyv[base + r] != 0u);
            m = g_rowmask[inst * 1000 + r];
            dact = (m >> (r >> 6)) & 1u;
        }
        srm[r] = m;
        sdiagw[r] = dact ? g_sup[(size_t)(inst * 1000 + r) * NW + (r >> 6)] : 0ULL;
        unsigned bv = __ballot_sync(0xffffffffu, valid);
        unsigned bd = __ballot_sync(0xffffffffu, dact);
        if (lane == 0) { sv[wid] = bv; sd[wid] = bd; }
    }
    __syncthreads();
    if (t < NW) {
        skeep[t]  = (unsigned long long)sv[2 * t] | ((unsigned long long)sv[2 * t + 1] << 32);
        sdmask[t] = (unsigned long long)sd[2 * t] | ((unsigned long long)sd[2 * t + 1] << 32);
    }
    __syncthreads();

    const int NCH = (k + 63) >> 6;

    unsigned long long p0 = 0, p1 = 0;
    if (wid > 0 && wid < NW) {
        int r0 = lane, r1 = lane + 32;
        if (r0 < k && ((srm[r0] >> wid) & 1u))
            p0 = g_sup[(size_t)(inst * 1000 + r0) * NW + wid];
        if (r1 < k && ((srm[r1] >> wid) & 1u))
            p1 = g_sup[(size_t)(inst * 1000 + r1) * NW + wid];
    }

    for (int c = 0; c < NCH; c++) {
        if (t == 0) {
            unsigned long long alive = skeep[c];
            unsigned long long dm = sdmask[c];
            while (dm) {
                int bidx[8]; unsigned long long rw[8]; int cnt = 0;
                #pragma unroll
                for (int e = 0; e < 8; e++) {
                    if (!dm) break;
                    int b = __ffsll((long long)dm) - 1;
                    dm &= dm - 1ULL;
                    bidx[cnt] = b;
                    rw[cnt] = sdiagw[c * 64 + b];
                    cnt++;
                }
                for (int e = 0; e < cnt; e++)
                    if ((alive >> bidx[e]) & 1ULL) alive &= ~rw[e];
            }
            skeep[c] = alive;
            s_alive = alive;
        }
        __syncthreads();
        const unsigned long long alive = s_alive;

        if (wid < NW) {
            unsigned long long v = 0;
            if (wid > c) {
                if ((alive >> lane) & 1ULL)        v  = p0;
                if ((alive >> (lane + 32)) & 1ULL) v |= p1;
            }

            p0 = p1 = 0;
            int cn = c + 1;
            if (cn < NCH && wid > cn) {
                int r0 = cn * 64 + lane, r1 = r0 + 32;
                if (r0 < k && ((srm[r0] >> wid) & 1u))
                    p0 = g_sup[(size_t)(inst * 1000 + r0) * NW + wid];
                if (r1 < k && ((srm[r1] >> wid) & 1u))
                    p1 = g_sup[(size_t)(inst * 1000 + r1) * NW + wid];
            }

            unsigned lo = __reduce_or_sync(0xffffffffu, (unsigned)v);
            unsigned hi = __reduce_or_sync(0xffffffffu, (unsigned)(v >> 32));
            if (lane == 0) {
                unsigned long long vv = ((unsigned long long)hi << 32) | lo;
                if (vv) skeep[wid] &= ~vv;
            }
        }
        __syncthreads();
    }

    if (t < NW) g_keepbits[inst * NW + t] = skeep[t];
}

// ================= Kernel 3: rank kept candidates (1 block per img,lev) ====
__global__ void __launch_bounds__(1024, 1)
final_kernel(float* __restrict__ out) {
    __shared__ unsigned long long klist[K_ALL];
    __shared__ int lvbase[NLEV + 1];
    __shared__ int warpsum[32];

    const int inst = blockIdx.x;
    const int img = inst / NLEV, mylev = inst % NLEV;
    const int t = threadIdx.x;
    const int wid = t >> 5, lane = t & 31;

    if (t == 0) lvbase[0] = 0;
    __syncthreads();

    // compact all 5 kept lists for this image (redundant across 5 blocks; cheap)
    for (int lev = 0; lev < NLEV; lev++) {
        const int k = c_k[lev], soff = c_soff[lev];
        bool kept = false;
        unsigned long long key = 0ULL;
        if (t < k) {
            unsigned long long kb = g_keepbits[(img * NLEV + lev) * NW + (t >> 6)];
            if ((kb >> (t & 63)) & 1ULL) {
                int slot = soff + t;
                kept = true;
                key = ((unsigned long long)g_keyv[img * K_ALL + slot] << 32) |
                      (unsigned)(~(unsigned)slot);
            }
        }
        unsigned bm = __ballot_sync(0xffffffffu, kept);
        if (lane == 0) warpsum[wid] = __popc(bm);
        __syncthreads();
        if (t < 32) {
            int v = warpsum[t];
            for (int d = 1; d < 32; d <<= 1) {
                int o = __shfl_up_sync(0xffffffffu, v, d);
                if (t >= d) v += o;
            }
            warpsum[t] = v;   // inclusive
            if (t == 31) lvbase[lev + 1] = lvbase[lev] + v;
        }
        __syncthreads();
        if (kept) {
            int pos = lvbase[lev] + (wid ? warpsum[wid - 1] : 0) +
                      __popc(bm & ((1u << lane) - 1u));
            klist[pos] = key;
        }
        __syncthreads();
    }

    const int C = lvbase[NLEV];

    // rank only this block's level
    for (int c = lvbase[mylev] + t; c < lvbase[mylev + 1]; c += 1024) {
        unsigned long long key = klist[c];
        int rank = c - lvbase[mylev];
        #pragma unroll
        for (int l2 = 0; l2 < NLEV; l2++) {
            if (l2 == mylev) continue;
            int lo = lvbase[l2], hi = lvbase[l2 + 1];
            while (lo < hi) {
                int mid = (lo + hi) >> 1;
                if (klist[mid] > key) lo = mid + 1; else hi = mid;
            }
            rank += lo - lvbase[l2];
        }
        if (rank < POST_N) {
            int slot = (int)(~(unsigned)key);
            float4 b = g_boxv[img * K_ALL + slot];
            float sc = g_scorev[img * K_ALL + slot];
            float* ob = out + (size_t)(img * POST_N + rank) * 4;
            ob[0] = b.x; ob[1] = b.y; ob[2] = b.z; ob[3] = b.w;
            out[BATCH * POST_N * 4 + img * POST_N + rank] = sc;
        }
    }

    // lev-0 block: zero the tail + reset maxc for next replay
    if (mylev == 0) {
        for (int x = C + t; x < POST_N; x += 1024) {
            float* ob = out + (size_t)(img * POST_N + x) * 4;
            ob[0] = 0.f; ob[1] = 0.f; ob[2] = 0.f; ob[3] = 0.f;
            out[BATCH * POST_N * 4 + img * POST_N + x] = 0.f;
        }
        if (t == 0) g_maxc[img] = 0;
    }
}

// ================= launch ====================
extern "C" void kernel_launch(void* const* d_in, const int* in_sizes, int n_in,
                              void* d_out, int out_size) {
    const float*  obj     = (const float*) d_in[0];   // [4, 159882]
    const float4* deltas  = (const float4*)d_in[1];   // [4, 159882, 4]
    const float4* anchors = (const float4*)d_in[2];   // [159882, 4]
    float* out = (float*)d_out;                       // boxes[4,1000,4] ++ scores[4,1000]

    cudaFuncSetAttribute(select_kernel, cudaFuncAttributeMaxDynamicSharedMemorySize, 106496);

    const int nelem = BATCH * A_TOTAL;                // 639528 = 4 * 159882
    hist_kernel<<<(nelem / 4 + 255) / 256, 256>>>(obj);
    select_kernel<<<NINST, 1024, 106496>>>(obj, deltas, anchors);
    fillscan_kernel<<<NINST * FILL_RB, 1024>>>();
    final_kernel<<<NINST, 1024>>>(out);
}